// round 6
// baseline (speedup 1.0000x reference)
#include <cuda_runtime.h>
#include <cstdint>

#define N_NODES 50000
#define N_EDGES 640000
#define IN_CH   128
#define HID_CH  256
#define K_TOT   256
#define TILE_M  128
#define TILE_N  128
#define N_TILES 391             // ceil(50000/128)
#define CHUNK_K 16
#define N_CHUNKS 16
#define STAGES  4
#define PITCH   20              // floats per smem row: 16B-aligned, conflict-free

// Scratch (__device__ globals zero-initialized; pad rows of g_A never written).
__device__ float g_agg[N_NODES * IN_CH];
__device__ float g_cnt[N_NODES];
__device__ float g_Bt[HID_CH * K_TOT];             // Bt[n][k], tf32-rounded
__device__ float g_A[(N_TILES * TILE_M) * K_TOT];  // [mean | x], tf32-rounded

__device__ __forceinline__ uint32_t f2tf(float f) {
    uint32_t r;
    asm("cvt.rna.tf32.f32 %0, %1;" : "=r"(r) : "f"(f));
    return r;
}
__device__ __forceinline__ uint32_t smem_u32(const void* p) {
    return (uint32_t)__cvta_generic_to_shared(p);
}
__device__ __forceinline__ void cp16(uint32_t dst, const void* src) {
    asm volatile("cp.async.ca.shared.global [%0], [%1], 16;"
                 :: "r"(dst), "l"(src) : "memory");
}

// ---------------------------------------------------------------------------
// Kernel 1: zero accumulators (float4 stores).
// ---------------------------------------------------------------------------
__global__ void zero_kernel() {
    int idx = blockIdx.x * blockDim.x + threadIdx.x;
    int stride = gridDim.x * blockDim.x;
    const int total4 = (N_NODES * IN_CH) / 4;
    float4 z = make_float4(0.f, 0.f, 0.f, 0.f);
    for (int i = idx; i < total4; i += stride)
        reinterpret_cast<float4*>(g_agg)[i] = z;
    for (int i = idx; i < N_NODES; i += stride) g_cnt[i] = 0.0f;
}

// ---------------------------------------------------------------------------
// Kernel 2: per-edge scatter (unchanged: red.global.add.v4.f32).
// ---------------------------------------------------------------------------
__global__ void scatter_kernel(const float* __restrict__ x,
                               const int* __restrict__ edge_index) {
    int warp = (blockIdx.x * blockDim.x + threadIdx.x) >> 5;
    int lane = threadIdx.x & 31;
    if (warp >= N_EDGES) return;

    int src = edge_index[warp];
    int dst = edge_index[N_EDGES + warp];

    float4 v = reinterpret_cast<const float4*>(x + (size_t)src * IN_CH)[lane];
    float* a = g_agg + (size_t)dst * IN_CH + lane * 4;
    asm volatile("red.global.add.v4.f32 [%0], {%1, %2, %3, %4};"
                 :: "l"(a), "f"(v.x), "f"(v.y), "f"(v.z), "f"(v.w) : "memory");
    if (lane == 0) atomicAdd(&g_cnt[dst], 1.0f);
}

// ---------------------------------------------------------------------------
// Kernel 3: transpose W into K-major Bt[n][k], tf32-rounded.
// ---------------------------------------------------------------------------
__global__ void transpose_kernel(const float* __restrict__ W_l,
                                 const float* __restrict__ W_r) {
    int k = blockIdx.x;
    int n = threadIdx.x;
    float v = (k < IN_CH) ? W_l[k * HID_CH + n] : W_r[(k - IN_CH) * HID_CH + n];
    g_Bt[n * K_TOT + k] = __uint_as_float(f2tf(v));
}

// ---------------------------------------------------------------------------
// Kernel 4: prep — g_A[node] = [tf32(agg/cnt) | tf32(x)]. Pad rows stay zero.
// 50000 rows x 64 float4. Grid 12500 x 256, exact.
// ---------------------------------------------------------------------------
__global__ void prep_kernel(const float* __restrict__ x) {
    int i = blockIdx.x * blockDim.x + threadIdx.x;
    int node = i >> 6;
    int j = i & 63;
    float4 v;
    if (j < 32) {
        v = reinterpret_cast<const float4*>(g_agg + (size_t)node * IN_CH)[j];
        float inv = 1.0f / fmaxf(g_cnt[node], 1.0f);
        v.x *= inv; v.y *= inv; v.z *= inv; v.w *= inv;
    } else {
        v = reinterpret_cast<const float4*>(x + (size_t)node * IN_CH)[j - 32];
    }
    v.x = __uint_as_float(f2tf(v.x));
    v.y = __uint_as_float(f2tf(v.y));
    v.z = __uint_as_float(f2tf(v.z));
    v.w = __uint_as_float(f2tf(v.w));
    reinterpret_cast<float4*>(g_A + (size_t)node * K_TOT)[j] = v;
}

// ---------------------------------------------------------------------------
// Kernel 5: tf32 mma.sync GEMM, cp.async 4-stage pipeline.
// Block 128x128 tile, grid (391, 2). 8 warps = 4(M) x 2(N); warp tile 32x64.
// K=256 in 16 chunks of 16; one __syncthreads per chunk; 3 chunks in flight.
// ---------------------------------------------------------------------------
#define STAGE_BYTES (TILE_M * PITCH * 4)              // 10240
#define OFF_BIAS 0
#define OFF_A    512
#define OFF_B    (OFF_A + STAGES * STAGE_BYTES)       // 41472
#define SMEM_BYTES (OFF_B + STAGES * STAGE_BYTES)     // 82432

__device__ __forceinline__ void mma_tf32(float* c, const uint32_t* a,
                                         uint32_t b0, uint32_t b1) {
    asm("mma.sync.aligned.m16n8k8.row.col.f32.tf32.tf32.f32 "
        "{%0,%1,%2,%3}, {%4,%5,%6,%7}, {%8,%9}, {%0,%1,%2,%3};"
        : "+f"(c[0]), "+f"(c[1]), "+f"(c[2]), "+f"(c[3])
        : "r"(a[0]), "r"(a[1]), "r"(a[2]), "r"(a[3]), "r"(b0), "r"(b1));
}

__global__ void __launch_bounds__(256, 2)
gemm_kernel(const float* __restrict__ b_l, float* __restrict__ out) {
    extern __shared__ char smem[];
    const int tid = threadIdx.x;
    const int wid = tid >> 5, lid = tid & 31;
    const int lrow = lid >> 2, lane4 = lid & 3;
    const int node0 = blockIdx.x * TILE_M;
    const int nblk0 = blockIdx.y * TILE_N;
    const int m_base = (wid & 3) * 32;
    const int n_base = (wid >> 2) * 64;

    float* bias_s = (float*)(smem + OFF_BIAS);
    if (tid < TILE_N) bias_s[tid] = b_l[nblk0 + tid];

    const uint32_t sA = smem_u32(smem + OFF_A);
    const uint32_t sB = smem_u32(smem + OFF_B);

    // cp.async mapping: 512 granules (16B) per operand per chunk; 2 per thread.
    const int r0 = tid >> 2, s0 = (tid & 3) * 4;                 // rows 0..63
    const int r1 = (tid + 256) >> 2, s1 = s0;                    // rows 64..127
    const float* gA0 = g_A + (size_t)(node0 + r0) * K_TOT + s0;
    const float* gA1 = g_A + (size_t)(node0 + r1) * K_TOT + s1;
    const float* gB0 = g_Bt + (size_t)(nblk0 + r0) * K_TOT + s0;
    const float* gB1 = g_Bt + (size_t)(nblk0 + r1) * K_TOT + s1;
    const uint32_t dA0 = (r0 * PITCH + s0) * 4, dA1 = (r1 * PITCH + s1) * 4;
    const uint32_t dB0 = dA0, dB1 = dA1;

    auto issue = [&](int c) {
        const int kc = c * CHUNK_K;
        const uint32_t bo = (uint32_t)(c & (STAGES - 1)) * STAGE_BYTES;
        cp16(sA + bo + dA0, gA0 + kc);
        cp16(sA + bo + dA1, gA1 + kc);
        cp16(sB + bo + dB0, gB0 + kc);
        cp16(sB + bo + dB1, gB1 + kc);
    };

    float acc[2][8][4];
    #pragma unroll
    for (int mi = 0; mi < 2; ++mi)
        #pragma unroll
        for (int ni = 0; ni < 8; ++ni)
            #pragma unroll
            for (int j = 0; j < 4; ++j) acc[mi][ni][j] = 0.f;

    // Prologue: 3 chunks in flight.
    issue(0); asm volatile("cp.async.commit_group;" ::: "memory");
    issue(1); asm volatile("cp.async.commit_group;" ::: "memory");
    issue(2); asm volatile("cp.async.commit_group;" ::: "memory");

    for (int c = 0; c < N_CHUNKS; ++c) {
        asm volatile("cp.async.wait_group 2;" ::: "memory");
        __syncthreads();

        // Refill the buffer consumed last iteration, then compute.
        if (c + 3 < N_CHUNKS) issue(c + 3);
        asm volatile("cp.async.commit_group;" ::: "memory");

        const float* As = (const float*)(smem + OFF_A + (c & (STAGES - 1)) * STAGE_BYTES);
        const float* Bs = (const float*)(smem + OFF_B + (c & (STAGES - 1)) * STAGE_BYTES);
        #pragma unroll
        for (int ks = 0; ks < 2; ++ks) {
            const int k0 = ks * 8;
            uint32_t a[2][4];
            #pragma unroll
            for (int mi = 0; mi < 2; ++mi) {
                const float* ap = As + (m_base + mi * 16 + lrow) * PITCH + k0 + lane4;
                a[mi][0] = __float_as_uint(ap[0]);
                a[mi][1] = __float_as_uint(ap[8 * PITCH]);
                a[mi][2] = __float_as_uint(ap[4]);
                a[mi][3] = __float_as_uint(ap[8 * PITCH + 4]);
            }
            #pragma unroll
            for (int ni = 0; ni < 8; ++ni) {
                const float* bp = Bs + (n_base + ni * 8 + lrow) * PITCH + k0 + lane4;
                uint32_t b0 = __float_as_uint(bp[0]);
                uint32_t b1 = __float_as_uint(bp[4]);
                mma_tf32(acc[0][ni], a[0], b0, b1);
                mma_tf32(acc[1][ni], a[1], b0, b1);
            }
        }
        __syncthreads();
    }

    // Epilogue: bias + store.
    #pragma unroll
    for (int mi = 0; mi < 2; ++mi) {
        int row = node0 + m_base + mi * 16 + lrow;
        #pragma unroll
        for (int ni = 0; ni < 8; ++ni) {
            int col = n_base + ni * 8 + lane4 * 2;
            float b0 = bias_s[col], b1 = bias_s[col + 1];
            if (row < N_NODES) {
                *reinterpret_cast<float2*>(out + (size_t)row * HID_CH + nblk0 + col) =
                    make_float2(acc[mi][ni][0] + b0, acc[mi][ni][1] + b1);
            }
            if (row + 8 < N_NODES) {
                *reinterpret_cast<float2*>(out + (size_t)(row + 8) * HID_CH + nblk0 + col) =
                    make_float2(acc[mi][ni][2] + b0, acc[mi][ni][3] + b1);
            }
        }
    }
}

// ---------------------------------------------------------------------------
// Launch. Inputs: x f32[50000*128], edge_index i32[2*640000],
// W_l f32[128*256], b_l f32[256], W_r f32[128*256]. Out f32[50000*256].
// ---------------------------------------------------------------------------
extern "C" void kernel_launch(void* const* d_in, const int* in_sizes, int n_in,
                              void* d_out, int out_size) {
    const float* x = (const float*)d_in[0];
    const int* edge_index = (const int*)d_in[1];
    const float* W_l = (const float*)d_in[2];
    const float* b_l = (const float*)d_in[3];
    const float* W_r = (const float*)d_in[4];
    float* out = (float*)d_out;

    cudaFuncSetAttribute(gemm_kernel,
                         cudaFuncAttributeMaxDynamicSharedMemorySize, SMEM_BYTES);

    zero_kernel<<<592, 256>>>();
    scatter_kernel<<<(N_EDGES + 7) / 8, 256>>>(x, edge_index);
    transpose_kernel<<<K_TOT, HID_CH>>>(W_l, W_r);
    prep_kernel<<<(N_NODES * 64) / 256, 256>>>(x);

    dim3 grid(N_TILES, 2);
    gemm_kernel<<<grid, 256, SMEM_BYTES>>>(b_l, out);
}